// round 9
// baseline (speedup 1.0000x reference)
#include <cuda_runtime.h>
#include <cuda_bf16.h>
#include <cstdint>

// ---------------------------------------------------------------------------
// Problem constants
// ---------------------------------------------------------------------------
#define BSZ    4096
#define ITEMW  10242
#define KTOT   10368      // padded GEMM K: 64 (genre) + 2240 (director) + 8064 (actor)
#define NCH    162        // chunks of 64; genre [0,1), director [1,36), actor [36,162)
#define NSLOT  6          // 0=genre, 1=director, 2..5=actor per k-split
#define PCX    64         // numerator columns per slot

// ---------------------------------------------------------------------------
// Device scratch (static globals; no allocations anywhere)
// ---------------------------------------------------------------------------
__device__ __align__(16) __nv_bfloat16 g_WT[64 * KTOT];     // fused weights [d][k]
__device__ float g_UF[3528 * 64];                            // user folds
__device__ float g_RF[6 * 64];                               // rate_tab @ item_W[0:64]
__device__ float g_part[(size_t)NSLOT * BSZ * PCX];          // GEMM partial numerators
__device__ float g_cnt[NSLOT * BSZ];                         // per-field bit counts
__device__ float g_X[BSZ * 64], g_Y[BSZ * 64];               // x, y vectors
__device__ float g_S[BSZ * 8];                               // per-row scalars (6 used)
__device__ float g_SP[4 * 1024 * 64];                        // per-CTA partials of s1..s4
__device__ float g_SP2[4 * 16 * 64];                         // stage-2 partials
__device__ float g_U[4 * 64];                                // u1..u4
__device__ float g_O3[64];                                   // edge-branch output row
__device__ int   g_dummy[1];

// ---------------------------------------------------------------------------
// Dummy kernel: keeps ncu's capture slot on k1_gemm.
// ---------------------------------------------------------------------------
__global__ void k_dummy() { g_dummy[0] = 1; }

// ---------------------------------------------------------------------------
// K0a: fold item-side weights into g_WT (bf16).
// ---------------------------------------------------------------------------
__global__ void __launch_bounds__(256) k0_wt(
    const float* __restrict__ genre_W, const float* __restrict__ director_W,
    const float* __restrict__ actor_W, const float* __restrict__ item_W)
{
    __shared__ float s_iw[64][65];
    __shared__ float s_w[64][65];
    int tid = threadIdx.x, d = tid & 63, q = tid >> 6;
    int blk = blockIdx.x;           // 0..161
    int kb = blk * 64;
    const float* W; int len, iwo, kr0;
    if (blk < 1)       { W = genre_W;    len = 25;   iwo = 64;  kr0 = 0;    }
    else if (blk < 36) { W = director_W; len = 2186; iwo = 128; kr0 = 64;   }
    else               { W = actor_W;    len = 8030; iwo = 192; kr0 = 2304; }

    #pragma unroll
    for (int j = q; j < 64; j += 4) s_iw[j][d] = item_W[(iwo + j) * 64 + d];
    #pragma unroll
    for (int kk = q; kk < 64; kk += 4) {
        int kr = kb + kk - kr0;
        s_w[kk][d] = (kr < len) ? W[(size_t)kr * 64 + d] : 0.f;
    }
    __syncthreads();

    float res[16] = {};
    #pragma unroll 4
    for (int j = 0; j < 64; ++j) {
        float a = s_iw[j][d];
        #pragma unroll
        for (int i = 0; i < 16; ++i) res[i] += s_w[q + 4 * i][j] * a;
    }
    __syncthreads();
    #pragma unroll
    for (int i = 0; i < 16; ++i) s_w[q + 4 * i][d] = res[i];
    __syncthreads();

    for (int j = tid; j < 2048; j += 256) {
        int dd = j >> 5, w = j & 31;
        __nv_bfloat162 h = __floats2bfloat162_rn(s_w[2 * w][dd], s_w[2 * w + 1][dd]);
        *(uint32_t*)&g_WT[(size_t)dd * KTOT + kb + 2 * w] = *(uint32_t*)&h;
    }
}

// ---------------------------------------------------------------------------
// K0b: fold user-side tables + rate table.
// ---------------------------------------------------------------------------
__global__ void __launch_bounds__(256) k0_user(
    const float* __restrict__ gender_tab, const float* __restrict__ age_tab,
    const float* __restrict__ occ_tab, const float* __restrict__ area_tab,
    const float* __restrict__ user_W, const float* __restrict__ rate_tab,
    const float* __restrict__ item_W)
{
    __shared__ float s_W[64][65];
    __shared__ float s_T[32][65];
    int tid = threadIdx.x, d = tid & 63, q = tid >> 6;
    int rb = blockIdx.x * 32;

    #pragma unroll
    for (int j = q; j < 64; j += 4) s_W[j][d] = user_W[(192 + j) * 64 + d];

    for (int j2 = tid; j2 < 32 * 64; j2 += 256) {
        int rr = j2 >> 6, col = j2 & 63, r = rb + rr;
        float v = 0.f;
        if (r < 98)         v = gender_tab[r * 64 + col];
        else if (r < 105)   v = age_tab[(r - 98) * 64 + col];
        else if (r < 126)   v = occ_tab[(r - 105) * 64 + col];
        else if (r < 3528)  v = area_tab[(size_t)(r - 126) * 64 + col];
        else if (r < 3534)  v = rate_tab[(r - 3528) * 64 + col];
        s_T[rr][col] = v;
    }
    __syncthreads();

    for (int rr = q; rr < 32; rr += 4) {
        int r = rb + rr;
        if (r >= 3534) continue;
        float v = 0.f;
        if (r >= 126 && r < 3528) {
            #pragma unroll 16
            for (int j = 0; j < 64; ++j) v += s_T[rr][j] * s_W[j][d];
        } else {
            const float* Wg = (r < 98) ? user_W : (r < 105) ? (user_W + 64 * 64)
                            : (r < 126) ? (user_W + 128 * 64) : item_W;
            #pragma unroll 16
            for (int j = 0; j < 64; ++j) v += s_T[rr][j] * Wg[j * 64 + d];
        }
        if (r < 3528) g_UF[(size_t)r * 64 + d] = v;
        else          g_RF[(r - 3528) * 64 + d] = v;
    }
}

// ---------------------------------------------------------------------------
// K1: HBM-bound bits GEMM. M=32 tiles, 3 CTAs/SM, 3-stage cp.async B ring,
// 2-deep A register prefetch, counts via integer redux (N=64 MMA).
//   grid (128 row-tiles, 4 k-splits):
//     sp0 chunks [0,40): slots 0(genre),1(director),2(actor head)
//     sp1 [40,82)->3, sp2 [82,122)->4, sp3 [122,162)->5
// ---------------------------------------------------------------------------
#define ASTR 144   // smem row stride in bytes (64 bf16 + 8 pad)

__device__ __forceinline__ void cp16(uint32_t dst, const void* src) {
    asm volatile("cp.async.cg.shared.global [%0], [%1], 16;\n" :: "r"(dst), "l"(src));
}
__device__ __forceinline__ uint32_t redux_add(uint32_t v) {
    uint32_t t;
    asm("redux.sync.add.u32 %0, %1, 0xffffffff;" : "=r"(t) : "r"(v));
    return t;
}
__device__ __forceinline__ void ldsm4(uint32_t& r0, uint32_t& r1, uint32_t& r2, uint32_t& r3,
                                      uint32_t addr) {
    asm volatile("ldmatrix.sync.aligned.m8n8.x4.shared.b16 {%0,%1,%2,%3}, [%4];\n"
                 : "=r"(r0), "=r"(r1), "=r"(r2), "=r"(r3) : "r"(addr));
}

__device__ __forceinline__ void prefA(const int* __restrict__ item, int rt, int c,
                                      int tid, int (&R)[8])
{
    int base, end;
    if (c < 1)       { base = 1;                    end = 26;    }
    else if (c < 36) { base = 26 + (c - 1) * 64;    end = 2212;  }
    else             { base = 2212 + (c - 36) * 64; end = 10242; }
    const bool full = (base + 64) <= end;   // note: partial path covers genre (odd base)

    #pragma unroll
    for (int it = 0; it < 4; ++it) {
        int idx2 = it * 512 + tid * 2;          // element pair in [0,2048)
        int row = idx2 >> 6, kk = idx2 & 63;
        int col = base + kk;
        const int* p = item + (long)(rt * 32 + row) * ITEMW + col;
        if (full) {
            int2 v = *(const int2*)p;           // 8-B aligned (base even, kk even)
            R[2 * it] = v.x; R[2 * it + 1] = v.y;
        } else {
            R[2 * it]     = (col < end)     ? p[0] : 0;
            R[2 * it + 1] = (col + 1 < end) ? p[1] : 0;
        }
    }
}

// store A bits (exact bf16 via bit-select) and accumulate integer counts.
// For iteration it, row = it*8 + warp -> redux over lanes gives row count.
__device__ __forceinline__ void commitA(const int (&R)[8], uint8_t* As, int tid,
                                        uint32_t (&cnt)[4])
{
    #pragma unroll
    for (int it = 0; it < 4; ++it) {
        int idx2 = it * 512 + tid * 2;
        int row = idx2 >> 6, kk = idx2 & 63;
        uint32_t h = (R[2 * it] ? 0x3F80u : 0u) | (R[2 * it + 1] ? 0x3F800000u : 0u);
        *(uint32_t*)(As + row * ASTR + kk * 2) = h;
        cnt[it] += (uint32_t)(R[2 * it] + R[2 * it + 1]);
    }
}

__device__ __forceinline__ void issueB(int c, uint32_t msu, int tid)
{
    const char* wt = (const char*)g_WT;
    size_t koff = (size_t)c * 128;   // kbase*2 bytes
    #pragma unroll
    for (int it = 0; it < 2; ++it) {
        int j = it * 256 + tid;
        int dd = j >> 3, w8 = j & 7;
        cp16(msu + dd * ASTR + w8 * 16, wt + (size_t)dd * (KTOT * 2) + koff + w8 * 16);
    }
    asm volatile("cp.async.commit_group;\n" ::: "memory");
}

__device__ __forceinline__ void k1_mma32(uint32_t asu, uint32_t msu,
                                         int a_off, int b_off, float (&acc)[2][4])
{
    #pragma unroll
    for (int ks = 0; ks < 4; ++ks) {
        uint32_t a0, a1, a2, a3, p0, p1, p2, p3;
        ldsm4(a0, a1, a2, a3, asu + a_off + ks * 32);
        ldsm4(p0, p1, p2, p3, msu + b_off + ks * 32);   // n-tiles wg, wg+4
        #define HM(ACC, B0, B1)                                                   \
            asm volatile(                                                         \
                "mma.sync.aligned.m16n8k16.row.col.f32.bf16.bf16.f32 "            \
                "{%0,%1,%2,%3}, {%4,%5,%6,%7}, {%8,%9}, {%0,%1,%2,%3};\n"         \
                : "+f"(ACC[0]), "+f"(ACC[1]), "+f"(ACC[2]), "+f"(ACC[3])          \
                : "r"(a0), "r"(a1), "r"(a2), "r"(a3), "r"(B0), "r"(B1))
        HM(acc[0], p0, p1);
        HM(acc[1], p2, p3);
        #undef HM
    }
}

__device__ __forceinline__ void flushAC(float (&acc)[2][4], uint32_t (&cnt)[4], int slot,
                                        int rt, int lane, int w, int wm, int wg)
{
    int row = rt * 32 + wm * 16 + (lane >> 2);
    int tg2 = 2 * (lane & 3);
    float* b0 = g_part + ((size_t)slot * BSZ + row) * PCX;
    float* b8 = g_part + ((size_t)slot * BSZ + row + 8) * PCX;
    #pragma unroll
    for (int li = 0; li < 2; ++li) {
        int col = (wg + 4 * li) * 8 + tg2;
        b0[col] = acc[li][0]; b0[col + 1] = acc[li][1];
        b8[col] = acc[li][2]; b8[col + 1] = acc[li][3];
        acc[li][0] = acc[li][1] = acc[li][2] = acc[li][3] = 0.f;
    }
    #pragma unroll
    for (int it = 0; it < 4; ++it) {
        uint32_t t = redux_add(cnt[it]);
        if (lane == 0) g_cnt[slot * BSZ + rt * 32 + it * 8 + w] = (float)t;
        cnt[it] = 0;
    }
}

// pipelined step: commit A(c), prefetch A(c+2), wait B(c) (leave B(c+1) in
// flight), barrier, issue B(c+2), MMA(c).
#define STEP(C, S, R)                                                        \
    do {                                                                     \
        commitA(R, As[S], tid, cnt);                                         \
        if ((C) + 2 < c1) prefA(item, rt, (C) + 2, tid, R);                  \
        if ((C) + 2 < c1) { asm volatile("cp.async.wait_group 1;\n" ::: "memory"); } \
        else              { asm volatile("cp.async.wait_group 0;\n" ::: "memory"); } \
        __syncthreads();                                                     \
        if ((C) + 2 < c1) issueB((C) + 2, msu[((C) + 2) % 3], tid);          \
        k1_mma32(asu[S], msu[(C) % 3], a_off, b_off, acc);                   \
    } while (0)

__global__ void __launch_bounds__(256, 3) k1_gemm(const int* __restrict__ item)
{
    __shared__ __align__(16) uint8_t As[2][32 * ASTR];
    __shared__ __align__(16) uint8_t Ms[3][64 * ASTR];
    int tid = threadIdx.x, lane = tid & 31, w = tid >> 5;
    int wm = w & 1, wg = w >> 1;     // 2 m-tiles x 4 n-groups
    int rt = blockIdx.x;             // 0..127 (32-row tiles)
    int sp = blockIdx.y;
    int c0, c1;
    if (sp == 0)      { c0 = 0;   c1 = 40;  }
    else if (sp == 1) { c0 = 40;  c1 = 82;  }
    else if (sp == 2) { c0 = 82;  c1 = 122; }
    else              { c0 = 122; c1 = 162; }

    uint32_t asu[2] = { (uint32_t)__cvta_generic_to_shared(As[0]),
                        (uint32_t)__cvta_generic_to_shared(As[1]) };
    uint32_t msu[3] = { (uint32_t)__cvta_generic_to_shared(Ms[0]),
                        (uint32_t)__cvta_generic_to_shared(Ms[1]),
                        (uint32_t)__cvta_generic_to_shared(Ms[2]) };

    // ldmatrix per-thread offsets
    int a_off = (wm * 16 + (lane & 15)) * ASTR + ((lane & 16) ? 16 : 0);
    int tsel  = (lane >> 4) & 1;
    int col8  = ((lane >> 3) & 1) * 16;
    int b_off = ((wg + 4 * tsel) * 8 + (lane & 7)) * ASTR + col8;

    float acc[2][4] = {};
    uint32_t cnt[4] = {};
    int R0[8], R1[8];

    issueB(c0,     msu[c0 % 3],       tid);
    issueB(c0 + 1, msu[(c0 + 1) % 3], tid);
    prefA(item, rt, c0,     tid, R0);
    prefA(item, rt, c0 + 1, tid, R1);

    if (sp == 0) {
        for (int c = 0; c < 40; c += 2) {
            STEP(c, 0, R0);
            if (c == 0) flushAC(acc, cnt, 0, rt, lane, w, wm, wg);        // genre
            STEP(c + 1, 1, R1);
            if (c + 1 == 35) flushAC(acc, cnt, 1, rt, lane, w, wm, wg);   // director
        }
        flushAC(acc, cnt, 2, rt, lane, w, wm, wg);                        // actor head
    } else {
        for (int c = c0; c < c1; c += 2) {
            STEP(c, 0, R0);
            STEP(c + 1, 1, R1);
        }
        flushAC(acc, cnt, 2 + sp, rt, lane, w, wm, wg);
    }
}

// ---------------------------------------------------------------------------
// K2: reduce partial slots, finalize x / y / edge, per-row scalars,
// s-vector partials. 4 rows per CTA, 1024 CTAs.
// ---------------------------------------------------------------------------
__global__ void __launch_bounds__(256) k2_finalize(
    const int* __restrict__ user_emb, const int* __restrict__ item,
    const int* __restrict__ edge_emb,
    const float* __restrict__ user_b, const float* __restrict__ item_b,
    const float* __restrict__ edges_tab,
    const float* __restrict__ uu_w, const float* __restrict__ ui_w,
    const float* __restrict__ iu_w, const float* __restrict__ ii_w)
{
    int tid = threadIdx.x, lane = tid & 31, warp = tid >> 5;
    int rr = tid >> 6, d = tid & 63;
    int row = blockIdx.x * 4 + rr;

    float ng = g_part[((size_t)0 * BSZ + row) * PCX + d];
    float nd = g_part[((size_t)1 * BSZ + row) * PCX + d];
    float na = g_part[((size_t)2 * BSZ + row) * PCX + d]
             + g_part[((size_t)3 * BSZ + row) * PCX + d]
             + g_part[((size_t)4 * BSZ + row) * PCX + d]
             + g_part[((size_t)5 * BSZ + row) * PCX + d];
    float cg = g_cnt[0 * BSZ + row];
    float cd = g_cnt[1 * BSZ + row];
    float ca = g_cnt[2 * BSZ + row] + g_cnt[3 * BSZ + row]
             + g_cnt[4 * BSZ + row] + g_cnt[5 * BSZ + row];

    int ri = item[(long)row * ITEMW];
    float y = (g_RF[ri * 64 + d] + ng / cg + nd / cd + na / ca + item_b[d]) * 0.12f;

    int gi = user_emb[row * 4 + 0], ai = user_emb[row * 4 + 1];
    int oi = user_emb[row * 4 + 2], ari = user_emb[row * 4 + 3];
    float x = (g_UF[gi * 64 + d] + g_UF[(98 + ai) * 64 + d] + g_UF[(105 + oi) * 64 + d]
             + g_UF[(size_t)(126 + ari) * 64 + d] + user_b[d]) * 0.12f;
    float e = edges_tab[edge_emb[row] * 64 + d] * 0.12f;

    g_X[row * 64 + d] = x;
    g_Y[row * 64 + d] = y;

    __shared__ float sx[4][64], sy[4][64];
    __shared__ float red[8][6], srow[4][6];
    sx[rr][d] = x; sy[rr][d] = y;

    float xe = x * e, ye = y * e;
    float pr[6] = { xe * uu_w[d], xe * ui_w[d], ye * ui_w[d],
                    ye * ii_w[d], ye * iu_w[d], xe * iu_w[d] };
    #pragma unroll
    for (int o = 16; o; o >>= 1) {
        #pragma unroll
        for (int j = 0; j < 6; ++j) pr[j] += __shfl_xor_sync(0xffffffffu, pr[j], o);
    }
    if (lane == 0) {
        #pragma unroll
        for (int j = 0; j < 6; ++j) red[warp][j] = pr[j];
    }
    __syncthreads();
    if (tid < 24) {
        int r2 = tid / 6, j = tid % 6;
        float v = red[2 * r2][j] + red[2 * r2 + 1][j];
        srow[r2][j] = v;
        g_S[(size_t)(blockIdx.x * 4 + r2) * 8 + j] = v;
    }
    __syncthreads();
    if (tid < 64) {
        float s1 = 0, s2 = 0, s3 = 0, s4 = 0;
        #pragma unroll
        for (int r2 = 0; r2 < 4; ++r2) {
            float xv = sx[r2][tid], yv = sy[r2][tid];
            s1 += srow[r2][0] * xv;   // x_xx * x
            s2 += srow[r2][2] * yv;   // x_xy_y * y
            s3 += srow[r2][3] * yv;   // y_yy * y
            s4 += srow[r2][5] * xv;   // y_yx_x * x
        }
        g_SP[(0 * 1024 + blockIdx.x) * 64 + tid] = s1;
        g_SP[(1 * 1024 + blockIdx.x) * 64 + tid] = s2;
        g_SP[(2 * 1024 + blockIdx.x) * 64 + tid] = s3;
        g_SP[(3 * 1024 + blockIdx.x) * 64 + tid] = s4;
    }
}

// ---------------------------------------------------------------------------
// K3a: reduce 1024 s-vector partials to 16 (parallel over 16 CTAs)
// ---------------------------------------------------------------------------
__global__ void __launch_bounds__(256) k3a_reduce()
{
    int tid = threadIdx.x, v = tid >> 6, d = tid & 63, b = blockIdx.x;
    float s = 0.f;
    #pragma unroll 8
    for (int i = b * 64; i < b * 64 + 64; ++i)
        s += g_SP[((size_t)v * 1024 + i) * 64 + d];
    g_SP2[(v * 16 + b) * 64 + d] = s;
}

// ---------------------------------------------------------------------------
// K3b: final reduce + u1..u4 matvecs + edge branch
// ---------------------------------------------------------------------------
__global__ void __launch_bounds__(320) k3b_final(
    const float* __restrict__ uu_W1, const float* __restrict__ ui_W1,
    const float* __restrict__ ii_W1, const float* __restrict__ iu_W1,
    const float* __restrict__ edge_W, const float* __restrict__ edges_tab)
{
    __shared__ float sq[4][64];
    __shared__ float ev[64];
    int tid = threadIdx.x;
    if (tid < 256) {
        int v = tid >> 6, d = tid & 63;
        float tot = 0.f;
        #pragma unroll
        for (int b = 0; b < 16; ++b) tot += g_SP2[(v * 16 + b) * 64 + d];
        sq[v][d] = tot;
    } else {
        ev[tid - 256] = edges_tab[tid - 256] * 0.12f;
    }
    __syncthreads();
    if (tid < 256) {
        int v = tid >> 6, d = tid & 63;
        const float* W1 = (v == 0) ? uu_W1 : (v == 1) ? ui_W1 : (v == 2) ? ii_W1 : iu_W1;
        float u = 0.f;
        #pragma unroll
        for (int j = 0; j < 64; ++j) u += sq[v][j] * W1[j * 64 + d];
        g_U[v * 64 + d] = u;
    } else {
        int dd = tid - 256;
        float nv = 0.f;
        #pragma unroll
        for (int j = 0; j < 64; ++j) nv += ev[j] * edge_W[j * 64 + dd];
        nv = nv >= 0.f ? nv : 0.01f * nv;
        g_O3[dd] = 0.5f * (nv + ev[dd]);
    }
}

// ---------------------------------------------------------------------------
// K4: final elementwise assembly of the three outputs
// ---------------------------------------------------------------------------
__global__ void __launch_bounds__(256) k4_out(float* __restrict__ out)
{
    int idx = blockIdx.x * 256 + threadIdx.x;   // 0..262143
    int r = idx >> 6, d = idx & 63;
    float x_xx   = g_S[(size_t)r * 8 + 0];
    float x_xy_x = g_S[(size_t)r * 8 + 1];
    float y_yy   = g_S[(size_t)r * 8 + 3];
    float y_yx_y = g_S[(size_t)r * 8 + 4];
    float a1 = x_xx * g_U[d];         a1 = a1 >= 0.f ? a1 : 0.01f * a1;
    float a2 = x_xy_x * g_U[64 + d];  a2 = a2 >= 0.f ? a2 : 0.01f * a2;
    float b1 = y_yy * g_U[128 + d];   b1 = b1 >= 0.f ? b1 : 0.01f * b1;
    float b2 = y_yx_y * g_U[192 + d]; b2 = b2 >= 0.f ? b2 : 0.01f * b2;
    out[idx]          = ((a1 + a2) * 0.5f + g_X[idx]) * 0.5f;
    out[262144 + idx] = ((b1 + b2) * 0.5f + g_Y[idx]) * 0.5f;
    out[524288 + idx] = g_O3[d];
}

// ---------------------------------------------------------------------------
// launch
// ---------------------------------------------------------------------------
extern "C" void kernel_launch(void* const* d_in, const int* in_sizes, int n_in,
                              void* d_out, int out_size)
{
    const int*   user_emb   = (const int*)d_in[0];
    const int*   item_emb   = (const int*)d_in[1];
    const int*   edge_emb   = (const int*)d_in[2];
    const float* gender_tab = (const float*)d_in[3];
    const float* age_tab    = (const float*)d_in[4];
    const float* occ_tab    = (const float*)d_in[5];
    const float* area_tab   = (const float*)d_in[6];
    const float* user_W     = (const float*)d_in[7];
    const float* user_b     = (const float*)d_in[8];
    const float* rate_tab   = (const float*)d_in[9];
    const float* genre_W    = (const float*)d_in[10];
    const float* director_W = (const float*)d_in[11];
    const float* actor_W    = (const float*)d_in[12];
    const float* item_W     = (const float*)d_in[13];
    const float* item_b     = (const float*)d_in[14];
    const float* edges_tab  = (const float*)d_in[15];
    const float* uu_w       = (const float*)d_in[16];
    const float* ui_w       = (const float*)d_in[17];
    const float* iu_w       = (const float*)d_in[18];
    const float* ii_w       = (const float*)d_in[19];
    const float* edge_W     = (const float*)d_in[20];
    const float* uu_W1      = (const float*)d_in[21];
    const float* ui_W1      = (const float*)d_in[22];
    const float* iu_W1      = (const float*)d_in[23];
    const float* ii_W1      = (const float*)d_in[24];
    float* out = (float*)d_out;

    k_dummy<<<1, 1>>>();
    k0_wt<<<NCH, 256>>>(genre_W, director_W, actor_W, item_W);
    k0_user<<<111, 256>>>(gender_tab, age_tab, occ_tab, area_tab, user_W, rate_tab, item_W);
    k1_gemm<<<dim3(128, 4), 256>>>(item_emb);
    k2_finalize<<<1024, 256>>>(user_emb, item_emb, edge_emb, user_b, item_b, edges_tab,
                               uu_w, ui_w, iu_w, ii_w);
    k3a_reduce<<<16, 256>>>();
    k3b_final<<<1, 320>>>(uu_W1, ui_W1, ii_W1, iu_W1, edge_W, edges_tab);
    k4_out<<<1024, 256>>>(out);
}

// round 10
// speedup vs baseline: 1.2017x; 1.2017x over previous
#include <cuda_runtime.h>
#include <cuda_bf16.h>
#include <cstdint>

// ---------------------------------------------------------------------------
// Problem constants
// ---------------------------------------------------------------------------
#define BSZ    4096
#define ITEMW  10242
#define KT2    10496      // padded K: 128 (genre) + 2304 (director) + 8064 (actor)
#define NST    82         // 128-k steps; genre [0,1), director [1,19), actor [19,82)
#define NSLOT  5          // 0=genre, 1=director, 2..4=actor per k-split
#define PCX    64         // numerator columns per slot
#define ASTR2  272        // smem row stride bytes (128 bf16 + 16 pad)
#define TILEB  (64 * ASTR2)   // 17408 bytes per A/B stage

// ---------------------------------------------------------------------------
// Device scratch (static globals; no allocations anywhere)
// ---------------------------------------------------------------------------
__device__ __align__(16) __nv_bfloat16 g_WT[64 * KT2];      // fused weights [d][k]
__device__ float g_UF[3528 * 64];                            // user folds
__device__ float g_RF[6 * 64];                               // rate_tab @ item_W[0:64]
__device__ float g_part[(size_t)NSLOT * BSZ * PCX];          // GEMM partial numerators
__device__ float g_cnt2[NSLOT * BSZ * 2];                    // per-field counts (2 half-rows)
__device__ float g_X[BSZ * 64], g_Y[BSZ * 64];               // x, y vectors
__device__ float g_S[BSZ * 8];                               // per-row scalars (6 used)
__device__ float g_SP[4 * 1024 * 64];                        // per-CTA partials of s1..s4
__device__ float g_SP2[4 * 16 * 64];                         // stage-2 partials
__device__ float g_U[4 * 64];                                // u1..u4
__device__ float g_O3[64];                                   // edge-branch output row
__device__ int   g_dummy[1];

// ---------------------------------------------------------------------------
// Dummy kernel: keeps ncu's capture slot on k1_gemm.
// ---------------------------------------------------------------------------
__global__ void k_dummy() { g_dummy[0] = 1; }

// ---------------------------------------------------------------------------
// K0a: fold item-side weights into g_WT (bf16). 164 chunks of 64 k.
//   k layout: genre [0,128) kr0=0, director [128,2432) kr0=128,
//             actor [2432,10496) kr0=2432
// ---------------------------------------------------------------------------
__global__ void __launch_bounds__(256) k0_wt(
    const float* __restrict__ genre_W, const float* __restrict__ director_W,
    const float* __restrict__ actor_W, const float* __restrict__ item_W)
{
    __shared__ float s_iw[64][65];
    __shared__ float s_w[64][65];
    int tid = threadIdx.x, d = tid & 63, q = tid >> 6;
    int blk = blockIdx.x;           // 0..163
    int kb = blk * 64;
    const float* W; int len, iwo, kr0;
    if (blk < 2)       { W = genre_W;    len = 25;   iwo = 64;  kr0 = 0;    }
    else if (blk < 38) { W = director_W; len = 2186; iwo = 128; kr0 = 128;  }
    else               { W = actor_W;    len = 8030; iwo = 192; kr0 = 2432; }

    #pragma unroll
    for (int j = q; j < 64; j += 4) s_iw[j][d] = item_W[(iwo + j) * 64 + d];
    #pragma unroll
    for (int kk = q; kk < 64; kk += 4) {
        int kr = kb + kk - kr0;
        s_w[kk][d] = (kr >= 0 && kr < len) ? W[(size_t)kr * 64 + d] : 0.f;
    }
    __syncthreads();

    float res[16] = {};
    #pragma unroll 4
    for (int j = 0; j < 64; ++j) {
        float a = s_iw[j][d];
        #pragma unroll
        for (int i = 0; i < 16; ++i) res[i] += s_w[q + 4 * i][j] * a;
    }
    __syncthreads();
    #pragma unroll
    for (int i = 0; i < 16; ++i) s_w[q + 4 * i][d] = res[i];
    __syncthreads();

    for (int j = tid; j < 2048; j += 256) {
        int dd = j >> 5, w = j & 31;
        __nv_bfloat162 h = __floats2bfloat162_rn(s_w[2 * w][dd], s_w[2 * w + 1][dd]);
        *(uint32_t*)&g_WT[(size_t)dd * KT2 + kb + 2 * w] = *(uint32_t*)&h;
    }
}

// ---------------------------------------------------------------------------
// K0b: fold user-side tables + rate table.
// ---------------------------------------------------------------------------
__global__ void __launch_bounds__(256) k0_user(
    const float* __restrict__ gender_tab, const float* __restrict__ age_tab,
    const float* __restrict__ occ_tab, const float* __restrict__ area_tab,
    const float* __restrict__ user_W, const float* __restrict__ rate_tab,
    const float* __restrict__ item_W)
{
    __shared__ float s_W[64][65];
    __shared__ float s_T[32][65];
    int tid = threadIdx.x, d = tid & 63, q = tid >> 6;
    int rb = blockIdx.x * 32;

    #pragma unroll
    for (int j = q; j < 64; j += 4) s_W[j][d] = user_W[(192 + j) * 64 + d];

    for (int j2 = tid; j2 < 32 * 64; j2 += 256) {
        int rr = j2 >> 6, col = j2 & 63, r = rb + rr;
        float v = 0.f;
        if (r < 98)         v = gender_tab[r * 64 + col];
        else if (r < 105)   v = age_tab[(r - 98) * 64 + col];
        else if (r < 126)   v = occ_tab[(r - 105) * 64 + col];
        else if (r < 3528)  v = area_tab[(size_t)(r - 126) * 64 + col];
        else if (r < 3534)  v = rate_tab[(r - 3528) * 64 + col];
        s_T[rr][col] = v;
    }
    __syncthreads();

    for (int rr = q; rr < 32; rr += 4) {
        int r = rb + rr;
        if (r >= 3534) continue;
        float v = 0.f;
        if (r >= 126 && r < 3528) {
            #pragma unroll 16
            for (int j = 0; j < 64; ++j) v += s_T[rr][j] * s_W[j][d];
        } else {
            const float* Wg = (r < 98) ? user_W : (r < 105) ? (user_W + 64 * 64)
                            : (r < 126) ? (user_W + 128 * 64) : item_W;
            #pragma unroll 16
            for (int j = 0; j < 64; ++j) v += s_T[rr][j] * Wg[j * 64 + d];
        }
        if (r < 3528) g_UF[(size_t)r * 64 + d] = v;
        else          g_RF[(r - 3528) * 64 + d] = v;
    }
}

// ---------------------------------------------------------------------------
// K1: HBM-bound bits GEMM. M=64, K=128 per step (one barrier per 32 KB of A),
// 3-stage cp.async B ring (wait_group 1), 1-step A register prefetch,
// counts via packed integer accumulate + redux.
//   grid (64 row-tiles, 4 k-splits):
//     sp0 steps [0,19):  slot 0 (genre, step 0), slot 1 (director, 1..18)
//     sp1 [19,40)->2, sp2 [40,61)->3, sp3 [61,82)->4
// ---------------------------------------------------------------------------
__device__ __forceinline__ void cp16(uint32_t dst, const void* src) {
    asm volatile("cp.async.cg.shared.global [%0], [%1], 16;\n" :: "r"(dst), "l"(src));
}
__device__ __forceinline__ uint32_t redux_add(uint32_t v) {
    uint32_t t;
    asm("redux.sync.add.u32 %0, %1, 0xffffffff;" : "=r"(t) : "r"(v));
    return t;
}
__device__ __forceinline__ void ldsm4(uint32_t& r0, uint32_t& r1, uint32_t& r2, uint32_t& r3,
                                      uint32_t addr) {
    asm volatile("ldmatrix.sync.aligned.m8n8.x4.shared.b16 {%0,%1,%2,%3}, [%4];\n"
                 : "=r"(r0), "=r"(r1), "=r"(r2), "=r"(r3) : "r"(addr));
}

// A prefetch: one K=128 step = 64 rows x 128 cols of int32 bits.
// Thread mapping: idx2 = it*512 + tid*2 -> row = idx2>>7 = it*4 + (tid>>6),
// kk = idx2 & 127. Warp pair (2j, 2j+1) covers row halves.
__device__ __forceinline__ void prefA(const int* __restrict__ item, int rt, int s,
                                      int tid, int (&R)[32])
{
    int base, end;
    if (s == 0)      { base = 1;                     end = 26;    }
    else if (s < 19) { base = 26 + (s - 1) * 128;    end = 2212;  }
    else             { base = 2212 + (s - 19) * 128; end = 10242; }
    const bool full = (base + 128) <= end;

    #pragma unroll
    for (int it = 0; it < 16; ++it) {
        int idx2 = it * 512 + tid * 2;
        int row = idx2 >> 7, kk = idx2 & 127;
        int col = base + kk;
        const int* p = item + (long)(rt * 64 + row) * ITEMW + col;
        if (full) {
            int2 v = *(const int2*)p;     // 8-B aligned (base even, kk even)
            R[2 * it] = v.x; R[2 * it + 1] = v.y;
        } else {
            R[2 * it]     = (col < end)     ? p[0] : 0;
            R[2 * it + 1] = (col + 1 < end) ? p[1] : 0;
        }
    }
}

// store A bits (exact bf16 via bit-select); counts packed 4x8-bit per register
__device__ __forceinline__ void commitA(const int (&R)[32], uint32_t asu, int tid,
                                        uint32_t (&cnt4)[4])
{
    #pragma unroll
    for (int it = 0; it < 16; ++it) {
        int idx2 = it * 512 + tid * 2;
        int row = idx2 >> 7, kk = idx2 & 127;
        uint32_t h = (R[2 * it] ? 0x3F80u : 0u) | (R[2 * it + 1] ? 0x3F800000u : 0u);
        asm volatile("st.shared.b32 [%0], %1;\n" :: "r"(asu + row * ASTR2 + kk * 2), "r"(h));
        cnt4[it >> 2] += (uint32_t)(R[2 * it] + R[2 * it + 1]) << ((it & 3) * 8);
    }
}

// B stage: 64 d-rows x 128 k bf16 (256 B/row), 4 cp16 per thread
__device__ __forceinline__ void issueB(int s, uint32_t msu, int tid)
{
    const char* wt = (const char*)g_WT;
    size_t koff = (size_t)s * 256;
    #pragma unroll
    for (int it = 0; it < 4; ++it) {
        int j = it * 256 + tid;
        int dd = j >> 4, w16 = j & 15;
        cp16(msu + dd * ASTR2 + w16 * 16,
             wt + (size_t)dd * (KT2 * 2) + koff + w16 * 16);
    }
    asm volatile("cp.async.commit_group;\n" ::: "memory");
}

__device__ __forceinline__ void k1_mma(uint32_t asu, uint32_t msu,
                                       int a_off, int b_off0, int b_off1,
                                       float (&acc)[4][4])
{
    #pragma unroll
    for (int ks = 0; ks < 8; ++ks) {
        uint32_t a0, a1, a2, a3, p0, p1, p2, p3, q0, q1, q2, q3;
        ldsm4(a0, a1, a2, a3, asu + a_off + ks * 32);
        ldsm4(p0, p1, p2, p3, msu + b_off0 + ks * 32);   // n-tiles wg, wg+2
        ldsm4(q0, q1, q2, q3, msu + b_off1 + ks * 32);   // n-tiles wg+4, wg+6
        #define HM(ACC, B0, B1)                                                   \
            asm volatile(                                                         \
                "mma.sync.aligned.m16n8k16.row.col.f32.bf16.bf16.f32 "            \
                "{%0,%1,%2,%3}, {%4,%5,%6,%7}, {%8,%9}, {%0,%1,%2,%3};\n"         \
                : "+f"(ACC[0]), "+f"(ACC[1]), "+f"(ACC[2]), "+f"(ACC[3])          \
                : "r"(a0), "r"(a1), "r"(a2), "r"(a3), "r"(B0), "r"(B1))
        HM(acc[0], p0, p1);
        HM(acc[1], p2, p3);
        HM(acc[2], q0, q1);
        HM(acc[3], q2, q3);
        #undef HM
    }
}

__device__ __forceinline__ void flushAC(float (&acc)[4][4], uint32_t (&cnt4)[4], int slot,
                                        int rt, int lane, int w, int wm, int wg)
{
    int row = rt * 64 + wm * 16 + (lane >> 2);
    int tg2 = 2 * (lane & 3);
    float* b0 = g_part + ((size_t)slot * BSZ + row) * PCX;
    float* b8 = g_part + ((size_t)slot * BSZ + row + 8) * PCX;
    #pragma unroll
    for (int li = 0; li < 4; ++li) {
        int col = (wg + 2 * li) * 8 + tg2;
        b0[col] = acc[li][0]; b0[col + 1] = acc[li][1];
        b8[col] = acc[li][2]; b8[col + 1] = acc[li][3];
        acc[li][0] = acc[li][1] = acc[li][2] = acc[li][3] = 0.f;
    }
    // counts: warp w covers half (w&1) of rows it*4 + (w>>1)
    #pragma unroll
    for (int it = 0; it < 16; ++it) {
        uint32_t v = (cnt4[it >> 2] >> ((it & 3) * 8)) & 0xFFu;
        uint32_t t = redux_add(v);
        if (lane == 0)
            g_cnt2[(slot * BSZ + rt * 64 + it * 4 + (w >> 1)) * 2 + (w & 1)] = (float)t;
    }
    cnt4[0] = cnt4[1] = cnt4[2] = cnt4[3] = 0;
}

__global__ void __launch_bounds__(256, 2) k1_gemm(const int* __restrict__ item)
{
    extern __shared__ __align__(16) uint8_t smem[];
    // layout: A stages at 0, TILEB; B ring at 2*TILEB + slot*TILEB
    uint32_t sbase = (uint32_t)__cvta_generic_to_shared(smem);

    int tid = threadIdx.x, lane = tid & 31, w = tid >> 5;
    int wm = w & 3, wg = w >> 2;     // 4 m-tiles x 2 n-groups
    int rt = blockIdx.x, sp = blockIdx.y;
    int s0, s1;
    if (sp == 0)      { s0 = 0;  s1 = 19; }
    else if (sp == 1) { s0 = 19; s1 = 40; }
    else if (sp == 2) { s0 = 40; s1 = 61; }
    else              { s0 = 61; s1 = 82; }

    // ldmatrix per-thread offsets
    int a_off  = (wm * 16 + (lane & 15)) * ASTR2 + ((lane & 16) ? 16 : 0);
    int tsel   = (lane >> 4) & 1;
    int col8   = ((lane >> 3) & 1) * 16;
    int b_off0 = ((wg + 2 * tsel) * 8 + (lane & 7)) * ASTR2 + col8;
    int b_off1 = ((wg + 4 + 2 * tsel) * 8 + (lane & 7)) * ASTR2 + col8;

    float acc[4][4] = {};
    uint32_t cnt4[4] = {};
    int R[32];

    issueB(s0,     sbase + 2 * TILEB + (s0 % 3) * TILEB,       tid);
    issueB(s0 + 1, sbase + 2 * TILEB + ((s0 + 1) % 3) * TILEB, tid);
    prefA(item, rt, s0, tid, R);

    for (int s = s0; s < s1; ++s) {
        uint32_t asu = sbase + (s & 1) * TILEB;
        commitA(R, asu, tid, cnt4);
        if (s + 1 < s1) {
            prefA(item, rt, s + 1, tid, R);
            asm volatile("cp.async.wait_group 1;\n" ::: "memory");
        } else {
            asm volatile("cp.async.wait_group 0;\n" ::: "memory");
        }
        __syncthreads();
        if (s + 2 < s1) issueB(s + 2, sbase + 2 * TILEB + ((s + 2) % 3) * TILEB, tid);
        k1_mma(asu, sbase + 2 * TILEB + (s % 3) * TILEB, a_off, b_off0, b_off1, acc);
        if (sp == 0 && s == 0) flushAC(acc, cnt4, 0, rt, lane, w, wm, wg);   // genre
    }
    int final_slot = (sp == 0) ? 1 : (1 + sp);
    flushAC(acc, cnt4, final_slot, rt, lane, w, wm, wg);
}

// ---------------------------------------------------------------------------
// K2: reduce partial slots, finalize x / y / edge, per-row scalars,
// s-vector partials. 4 rows per CTA, 1024 CTAs.
// ---------------------------------------------------------------------------
__global__ void __launch_bounds__(256) k2_finalize(
    const int* __restrict__ user_emb, const int* __restrict__ item,
    const int* __restrict__ edge_emb,
    const float* __restrict__ user_b, const float* __restrict__ item_b,
    const float* __restrict__ edges_tab,
    const float* __restrict__ uu_w, const float* __restrict__ ui_w,
    const float* __restrict__ iu_w, const float* __restrict__ ii_w)
{
    int tid = threadIdx.x, lane = tid & 31, warp = tid >> 5;
    int rr = tid >> 6, d = tid & 63;
    int row = blockIdx.x * 4 + rr;

    float ng = g_part[((size_t)0 * BSZ + row) * PCX + d];
    float nd = g_part[((size_t)1 * BSZ + row) * PCX + d];
    float na = g_part[((size_t)2 * BSZ + row) * PCX + d]
             + g_part[((size_t)3 * BSZ + row) * PCX + d]
             + g_part[((size_t)4 * BSZ + row) * PCX + d];
    float cg = g_cnt2[(0 * BSZ + row) * 2] + g_cnt2[(0 * BSZ + row) * 2 + 1];
    float cd = g_cnt2[(1 * BSZ + row) * 2] + g_cnt2[(1 * BSZ + row) * 2 + 1];
    float ca = g_cnt2[(2 * BSZ + row) * 2] + g_cnt2[(2 * BSZ + row) * 2 + 1]
             + g_cnt2[(3 * BSZ + row) * 2] + g_cnt2[(3 * BSZ + row) * 2 + 1]
             + g_cnt2[(4 * BSZ + row) * 2] + g_cnt2[(4 * BSZ + row) * 2 + 1];

    int ri = item[(long)row * ITEMW];
    float y = (g_RF[ri * 64 + d] + ng / cg + nd / cd + na / ca + item_b[d]) * 0.12f;

    int gi = user_emb[row * 4 + 0], ai = user_emb[row * 4 + 1];
    int oi = user_emb[row * 4 + 2], ari = user_emb[row * 4 + 3];
    float x = (g_UF[gi * 64 + d] + g_UF[(98 + ai) * 64 + d] + g_UF[(105 + oi) * 64 + d]
             + g_UF[(size_t)(126 + ari) * 64 + d] + user_b[d]) * 0.12f;
    float e = edges_tab[edge_emb[row] * 64 + d] * 0.12f;

    g_X[row * 64 + d] = x;
    g_Y[row * 64 + d] = y;

    __shared__ float sx[4][64], sy[4][64];
    __shared__ float red[8][6], srow[4][6];
    sx[rr][d] = x; sy[rr][d] = y;

    float xe = x * e, ye = y * e;
    float pr[6] = { xe * uu_w[d], xe * ui_w[d], ye * ui_w[d],
                    ye * ii_w[d], ye * iu_w[d], xe * iu_w[d] };
    #pragma unroll
    for (int o = 16; o; o >>= 1) {
        #pragma unroll
        for (int j = 0; j < 6; ++j) pr[j] += __shfl_xor_sync(0xffffffffu, pr[j], o);
    }
    if (lane == 0) {
        #pragma unroll
        for (int j = 0; j < 6; ++j) red[warp][j] = pr[j];
    }
    __syncthreads();
    if (tid < 24) {
        int r2 = tid / 6, j = tid % 6;
        float v = red[2 * r2][j] + red[2 * r2 + 1][j];
        srow[r2][j] = v;
        g_S[(size_t)(blockIdx.x * 4 + r2) * 8 + j] = v;
    }
    __syncthreads();
    if (tid < 64) {
        float s1 = 0, s2 = 0, s3 = 0, s4 = 0;
        #pragma unroll
        for (int r2 = 0; r2 < 4; ++r2) {
            float xv = sx[r2][tid], yv = sy[r2][tid];
            s1 += srow[r2][0] * xv;   // x_xx * x
            s2 += srow[r2][2] * yv;   // x_xy_y * y
            s3 += srow[r2][3] * yv;   // y_yy * y
            s4 += srow[r2][5] * xv;   // y_yx_x * x
        }
        g_SP[(0 * 1024 + blockIdx.x) * 64 + tid] = s1;
        g_SP[(1 * 1024 + blockIdx.x) * 64 + tid] = s2;
        g_SP[(2 * 1024 + blockIdx.x) * 64 + tid] = s3;
        g_SP[(3 * 1024 + blockIdx.x) * 64 + tid] = s4;
    }
}

// ---------------------------------------------------------------------------
// K3a: reduce 1024 s-vector partials to 16 (parallel over 16 CTAs)
// ---------------------------------------------------------------------------
__global__ void __launch_bounds__(256) k3a_reduce()
{
    int tid = threadIdx.x, v = tid >> 6, d = tid & 63, b = blockIdx.x;
    float s = 0.f;
    #pragma unroll 8
    for (int i = b * 64; i < b * 64 + 64; ++i)
        s += g_SP[((size_t)v * 1024 + i) * 64 + d];
    g_SP2[(v * 16 + b) * 64 + d] = s;
}

// ---------------------------------------------------------------------------
// K3b: final reduce + u1..u4 matvecs + edge branch
// ---------------------------------------------------------------------------
__global__ void __launch_bounds__(320) k3b_final(
    const float* __restrict__ uu_W1, const float* __restrict__ ui_W1,
    const float* __restrict__ ii_W1, const float* __restrict__ iu_W1,
    const float* __restrict__ edge_W, const float* __restrict__ edges_tab)
{
    __shared__ float sq[4][64];
    __shared__ float ev[64];
    int tid = threadIdx.x;
    if (tid < 256) {
        int v = tid >> 6, d = tid & 63;
        float tot = 0.f;
        #pragma unroll
        for (int b = 0; b < 16; ++b) tot += g_SP2[(v * 16 + b) * 64 + d];
        sq[v][d] = tot;
    } else {
        ev[tid - 256] = edges_tab[tid - 256] * 0.12f;
    }
    __syncthreads();
    if (tid < 256) {
        int v = tid >> 6, d = tid & 63;
        const float* W1 = (v == 0) ? uu_W1 : (v == 1) ? ui_W1 : (v == 2) ? ii_W1 : iu_W1;
        float u = 0.f;
        #pragma unroll
        for (int j = 0; j < 64; ++j) u += sq[v][j] * W1[j * 64 + d];
        g_U[v * 64 + d] = u;
    } else {
        int dd = tid - 256;
        float nv = 0.f;
        #pragma unroll
        for (int j = 0; j < 64; ++j) nv += ev[j] * edge_W[j * 64 + dd];
        nv = nv >= 0.f ? nv : 0.01f * nv;
        g_O3[dd] = 0.5f * (nv + ev[dd]);
    }
}

// ---------------------------------------------------------------------------
// K4: final elementwise assembly of the three outputs
// ---------------------------------------------------------------------------
__global__ void __launch_bounds__(256) k4_out(float* __restrict__ out)
{
    int idx = blockIdx.x * 256 + threadIdx.x;   // 0..262143
    int r = idx >> 6, d = idx & 63;
    float x_xx   = g_S[(size_t)r * 8 + 0];
    float x_xy_x = g_S[(size_t)r * 8 + 1];
    float y_yy   = g_S[(size_t)r * 8 + 3];
    float y_yx_y = g_S[(size_t)r * 8 + 4];
    float a1 = x_xx * g_U[d];         a1 = a1 >= 0.f ? a1 : 0.01f * a1;
    float a2 = x_xy_x * g_U[64 + d];  a2 = a2 >= 0.f ? a2 : 0.01f * a2;
    float b1 = y_yy * g_U[128 + d];   b1 = b1 >= 0.f ? b1 : 0.01f * b1;
    float b2 = y_yx_y * g_U[192 + d]; b2 = b2 >= 0.f ? b2 : 0.01f * b2;
    out[idx]          = ((a1 + a2) * 0.5f + g_X[idx]) * 0.5f;
    out[262144 + idx] = ((b1 + b2) * 0.5f + g_Y[idx]) * 0.5f;
    out[524288 + idx] = g_O3[d];
}

// ---------------------------------------------------------------------------
// launch
// ---------------------------------------------------------------------------
extern "C" void kernel_launch(void* const* d_in, const int* in_sizes, int n_in,
                              void* d_out, int out_size)
{
    const int*   user_emb   = (const int*)d_in[0];
    const int*   item_emb   = (const int*)d_in[1];
    const int*   edge_emb   = (const int*)d_in[2];
    const float* gender_tab = (const float*)d_in[3];
    const float* age_tab    = (const float*)d_in[4];
    const float* occ_tab    = (const float*)d_in[5];
    const float* area_tab   = (const float*)d_in[6];
    const float* user_W     = (const float*)d_in[7];
    const float* user_b     = (const float*)d_in[8];
    const float* rate_tab   = (const float*)d_in[9];
    const float* genre_W    = (const float*)d_in[10];
    const float* director_W = (const float*)d_in[11];
    const float* actor_W    = (const float*)d_in[12];
    const float* item_W     = (const float*)d_in[13];
    const float* item_b     = (const float*)d_in[14];
    const float* edges_tab  = (const float*)d_in[15];
    const float* uu_w       = (const float*)d_in[16];
    const float* ui_w       = (const float*)d_in[17];
    const float* iu_w       = (const float*)d_in[18];
    const float* ii_w       = (const float*)d_in[19];
    const float* edge_W     = (const float*)d_in[20];
    const float* uu_W1      = (const float*)d_in[21];
    const float* ui_W1      = (const float*)d_in[22];
    const float* iu_W1      = (const float*)d_in[23];
    const float* ii_W1      = (const float*)d_in[24];
    float* out = (float*)d_out;

    const int k1_smem = 5 * TILEB;   // 2 A stages + 3 B stages = 87040 B
    cudaFuncSetAttribute(k1_gemm, cudaFuncAttributeMaxDynamicSharedMemorySize, k1_smem);

    k_dummy<<<1, 1>>>();
    k0_wt<<<164, 256>>>(genre_W, director_W, actor_W, item_W);
    k0_user<<<111, 256>>>(gender_tab, age_tab, occ_tab, area_tab, user_W, rate_tab, item_W);
    k1_gemm<<<dim3(64, 4), 256, k1_smem>>>(item_emb);
    k2_finalize<<<1024, 256>>>(user_emb, item_emb, edge_emb, user_b, item_b, edges_tab,
                               uu_w, ui_w, iu_w, ii_w);
    k3a_reduce<<<16, 256>>>();
    k3b_final<<<1, 320>>>(uu_W1, ui_W1, ii_W1, iu_W1, edge_W, edges_tab);
    k4_out<<<1024, 256>>>(out);
}